// round 14
// baseline (speedup 1.0000x reference)
#include <cuda_runtime.h>
#include <math.h>

// ---------------- scratch (static device globals) ---------------------------
__device__ float g_xg_f[16*128*1024];
__device__ float g_xg_b[16*128*1024];
__device__ float g_Wsl[2*8*256*128];   // per (dir,slice): k-major [256][128]
__device__ float g_hf [16*128*256];
__device__ float g_hb [16*128*256];
__device__ float g_o  [16*128*256];
__device__ float g_u  [2048*128];
__device__ float g_v  [2048*128];
__device__ float g_a  [2048*128];
__device__ float g_cb [2048*128];
__device__ float g_crf[16];
__device__ float g_selpart[512];

// ---------------- generic 64x64 SGEMM, z-paired: C = op(A) @ W^T ------------
// amode: 0 = A[row*lda+k]; 1 = word_emb[tokens[row]*256+k];
//        2 = k<256 ? g_o[row*256+k] : bio_emb[bio_gold[row]*64+(k-256)]
__global__ __launch_bounds__(256) void gemm_kernel(
    int K, int amode,
    const float* __restrict__ A_, const float* __restrict__ A2, int lda,
    const int*   __restrict__ tokens,
    const float* __restrict__ word_emb,
    const int*   __restrict__ bio_gold,
    const float* __restrict__ bio_emb,
    const float* __restrict__ W_, const float* __restrict__ W2, int ldw,
    const float* __restrict__ bias_, const float* __restrict__ bias2,
    int do_relu,
    float* __restrict__ C_, float* __restrict__ C2, int ldc)
{
    const float* A    = blockIdx.z ? A2    : A_;
    const float* W    = blockIdx.z ? W2    : W_;
    const float* bias = blockIdx.z ? bias2 : bias_;
    float*       C    = blockIdx.z ? C2    : C_;
    __shared__ __align__(16) float As[16][68];
    __shared__ __align__(16) float Bs[16][68];
    int tid = threadIdx.x;
    int tx = tid & 15, ty = tid >> 4;
    int row0 = blockIdx.y * 64, col0 = blockIdx.x * 64;
    float acc[4][4];
#pragma unroll
    for (int i = 0; i < 4; ++i)
#pragma unroll
        for (int j = 0; j < 4; ++j) acc[i][j] = 0.f;

    for (int k0 = 0; k0 < K; k0 += 16) {
#pragma unroll
        for (int l = 0; l < 4; ++l) {
            int e = tid + l * 256;
            int m = e >> 4, kk = e & 15;
            int row = row0 + m, k = k0 + kk;
            float v;
            if (amode == 0)      v = A[row * lda + k];
            else if (amode == 1) v = word_emb[tokens[row] * 256 + k];
            else                 v = (k < 256) ? g_o[row * 256 + k]
                                               : bio_emb[bio_gold[row] * 64 + (k - 256)];
            As[kk][m] = v;
            Bs[kk][m] = W[(col0 + m) * ldw + k];
        }
        __syncthreads();
#pragma unroll
        for (int kk = 0; kk < 16; ++kk) {
            float4 a4 = *(const float4*)&As[kk][ty << 2];
            float4 b4 = *(const float4*)&Bs[kk][tx << 2];
            acc[0][0]=fmaf(a4.x,b4.x,acc[0][0]); acc[0][1]=fmaf(a4.x,b4.y,acc[0][1]);
            acc[0][2]=fmaf(a4.x,b4.z,acc[0][2]); acc[0][3]=fmaf(a4.x,b4.w,acc[0][3]);
            acc[1][0]=fmaf(a4.y,b4.x,acc[1][0]); acc[1][1]=fmaf(a4.y,b4.y,acc[1][1]);
            acc[1][2]=fmaf(a4.y,b4.z,acc[1][2]); acc[1][3]=fmaf(a4.y,b4.w,acc[1][3]);
            acc[2][0]=fmaf(a4.z,b4.x,acc[2][0]); acc[2][1]=fmaf(a4.z,b4.y,acc[2][1]);
            acc[2][2]=fmaf(a4.z,b4.z,acc[2][2]); acc[2][3]=fmaf(a4.z,b4.w,acc[2][3]);
            acc[3][0]=fmaf(a4.w,b4.x,acc[3][0]); acc[3][1]=fmaf(a4.w,b4.y,acc[3][1]);
            acc[3][2]=fmaf(a4.w,b4.z,acc[3][2]); acc[3][3]=fmaf(a4.w,b4.w,acc[3][3]);
        }
        __syncthreads();
    }
#pragma unroll
    for (int i = 0; i < 4; ++i) {
        int row = row0 + (ty << 2) + i;
#pragma unroll
        for (int j = 0; j < 4; ++j) {
            int col = col0 + (tx << 2) + j;
            float v = acc[i][j];
            if (bias) v += bias[col];
            if (do_relu) v = fmaxf(v, 0.f);
            C[row * ldc + col] = v;
        }
    }
}

// ---------------- prep: W_hh -> per-(dir,slice) k-major slices --------------
__global__ __launch_bounds__(256) void prep_kernel(
    const float* __restrict__ Wf, const float* __restrict__ Wb)
{
    __shared__ float tile[32][33];
    int dir = blockIdx.z;
    const float* W = dir ? Wb : Wf;
    int R0 = blockIdx.x * 32;
    int k0 = blockIdx.y * 32;
    int g = R0 >> 8;
    int s = (R0 >> 5) & 7;
    int tx = threadIdx.x & 31, ty = threadIdx.x >> 5;
#pragma unroll
    for (int l = 0; l < 4; ++l)
        tile[ty + 8*l][tx] = W[(R0 + ty + 8*l) * 256 + k0 + tx];
    __syncthreads();
    float* dst = g_Wsl + ((dir*8 + s) << 15);
#pragma unroll
    for (int l = 0; l < 4; ++l)
        dst[(k0 + ty + 8*l) * 128 + g*32 + tx] = tile[tx][ty + 8*l];
}

// ---------------- DSMEM / mbarrier helpers ----------------------------------
__device__ __forceinline__ unsigned smem_u32(const void* p) {
    unsigned a;
    asm("{ .reg .u64 t; cvta.to.shared.u64 t, %1; cvt.u32.u64 %0, t; }"
        : "=r"(a) : "l"(p));
    return a;
}
__device__ __forceinline__ unsigned cta_rank() {
    unsigned r; asm("mov.u32 %0, %%cluster_ctarank;" : "=r"(r)); return r;
}
__device__ __forceinline__ void dsmem_st(unsigned laddr, int rank, float v) {
    unsigned raddr;
    asm volatile("mapa.shared::cluster.u32 %0, %1, %2;"
                 : "=r"(raddr) : "r"(laddr), "r"(rank));
    asm volatile("st.shared::cluster.f32 [%0], %1;"
                 :: "r"(raddr), "f"(v) : "memory");
}
__device__ __forceinline__ void mbar_arrive_remote(unsigned local_mbar, int rank) {
    unsigned raddr;
    asm volatile("mapa.shared::cluster.u32 %0, %1, %2;"
                 : "=r"(raddr) : "r"(local_mbar), "r"(rank));
    asm volatile("mbarrier.arrive.release.cluster.shared::cluster.b64 _, [%0];"
                 :: "r"(raddr) : "memory");
}
__device__ __forceinline__ void mbar_wait_cluster(unsigned mbar, unsigned parity) {
    asm volatile(
        "{\n\t"
        ".reg .pred P;\n\t"
        "WAIT_%=:\n\t"
        "mbarrier.try_wait.parity.acquire.cluster.shared::cta.b64 P, [%0], %1, 0x989680;\n\t"
        "@P bra.uni DONE_%=;\n\t"
        "bra.uni WAIT_%=;\n\t"
        "DONE_%=:\n\t"
        "}"
        :: "r"(mbar), "r"(parity) : "memory");
}

// ---------------- BiLSTM: mbarrier-synced cluster recurrence ----------------
// 16 clusters x 8 CTAs; CTA (rank=slice) owns 32 units for 2 batches.
__global__ void __cluster_dims__(8,1,1) __launch_bounds__(512) lstm_cluster_kernel()
{
    int slice = cta_rank();
    int cl  = blockIdx.x >> 3;       // 0..15
    int dir = cl >> 3, pair = cl & 7;
    const float* xg = dir ? g_xg_b : g_xg_f;
    float* hout     = dir ? g_hb : g_hf;
    extern __shared__ float sm[];
    float* mbarf = sm;                     // 16 B (mbarrier @ 8B align)
    float* ws    = sm + 4;                 // [256][128] weight slice (k-major)
    float* h_s   = sm + 4 + 32768;         // [2 phase][2 batch][256]
    float* part  = h_s + 1024;             // [8 q][2 b][4 gate][40] = 2560
    int tid = threadIdx.x;
    unsigned mbar = smem_u32(mbarf);

    if (tid == 0) {
        asm volatile("mbarrier.init.shared.b64 [%0], %1;" :: "r"(mbar), "r"(8u) : "memory");
    }
    {   // load weight slice once
        const float4* src = (const float4*)(g_Wsl + ((dir*8 + slice) << 15));
        float4* dst = (float4*)ws;
        for (int i = tid; i < 8192; i += 512) dst[i] = src[i];
    }
    // k-loop roles
    int rp = tid & 63, kq = tid >> 6;
    int r0 = rp << 1, kbase = kq << 5;
    int pw = kq*320 + (r0 >> 5)*40 + (r0 & 31);
    // gate-gather role (tid<256)
    int wq = tid >> 5, l = tid & 31;
    int ubl = l & 7, gate = l >> 3;
    int gub = wq*8 + ubl;
    int gb  = (gub >> 5) & 1, gu = gub & 31;
    int grd = gb*160 + gate*40 + gu;
    int gxrow = gate*256 + slice*32 + gu;
    int gbg = pair*2 + gb;
    // cell role: lanes l<8 of warps wq<8
    int cub = wq*8 + (l & 7);
    int cb2 = (cub >> 5) & 1, cu2 = cub & 31;
    int cbg = pair*2 + cb2;
    int choff = (cb2 << 8) + (slice << 5) + cu2;
    unsigned hs_base = smem_u32(h_s);
    float cst = 0.f;
    h_s[tid] = 0.f;                  // zero phase-0 buffer
    __syncthreads();
    // cluster-wide: mbarrier inits + h zeros visible before any remote arrive
    asm volatile("barrier.cluster.arrive.aligned;" ::: "memory");
    asm volatile("barrier.cluster.wait.aligned;"   ::: "memory");
    float xreg = 0.f;
    if (tid < 256) {
        int t0 = dir ? 127 : 0;
        xreg = xg[(((gbg << 7) + t0) << 10) + gxrow];
    }

    for (int step = 0; step < 128; ++step) {
        if (step) mbar_wait_cluster(mbar, (step - 1) & 1);
        int t = dir ? (127 - step) : step;
        int phase = step & 1;
        const float* hp = h_s + (phase << 9);

        float a00 = 0.f, a10 = 0.f, a01 = 0.f, a11 = 0.f;
        const float* wp = ws + r0;
#pragma unroll
        for (int kk = 0; kk < 32; kk += 4) {
            int k = kbase + kk;
            float4 ha4 = *(const float4*)&hp[k];
            float4 hb4 = *(const float4*)&hp[256 + k];
            float2 w0 = *(const float2*)&wp[(k + 0) << 7];
            float2 w1 = *(const float2*)&wp[(k + 1) << 7];
            float2 w2 = *(const float2*)&wp[(k + 2) << 7];
            float2 w3 = *(const float2*)&wp[(k + 3) << 7];
            a00 = fmaf(w0.x, ha4.x, a00); a10 = fmaf(w0.y, ha4.x, a10);
            a01 = fmaf(w0.x, hb4.x, a01); a11 = fmaf(w0.y, hb4.x, a11);
            a00 = fmaf(w1.x, ha4.y, a00); a10 = fmaf(w1.y, ha4.y, a10);
            a01 = fmaf(w1.x, hb4.y, a01); a11 = fmaf(w1.y, hb4.y, a11);
            a00 = fmaf(w2.x, ha4.z, a00); a10 = fmaf(w2.y, ha4.z, a10);
            a01 = fmaf(w2.x, hb4.z, a01); a11 = fmaf(w2.y, hb4.z, a11);
            a00 = fmaf(w3.x, ha4.w, a00); a10 = fmaf(w3.y, ha4.w, a10);
            a01 = fmaf(w3.x, hb4.w, a01); a11 = fmaf(w3.y, hb4.w, a11);
        }
        part[pw]       = a00; part[pw + 1]       = a10;
        part[pw + 160] = a01; part[pw + 160 + 1] = a11;
        __syncthreads();

        if (tid < 256) {
            float s = xreg;
#pragma unroll
            for (int q = 0; q < 8; ++q) s += part[q*320 + grd];
            float gi = __shfl_sync(0xffffffffu, s, ubl);
            float gf = __shfl_sync(0xffffffffu, s, 8 + ubl);
            float gg = __shfl_sync(0xffffffffu, s, 16 + ubl);
            float go = __shfl_sync(0xffffffffu, s, 24 + ubl);
            if (l < 8) {
                float si = 1.f / (1.f + expf(-gi));
                float sf = 1.f / (1.f + expf(-gf));
                float so = 1.f / (1.f + expf(-go));
                cst = sf * cst + si * tanhf(gg);
                float h = so * tanhf(cst);
                hout[(((cbg << 7) + t) << 8) + (slice << 5) + cu2] = h;
                unsigned dsta = hs_base + ((((phase ^ 1) << 9) + choff) << 2);
#pragma unroll
                for (int rk = 0; rk < 8; ++rk) dsmem_st(dsta, rk, h);
            }
        }
        __syncthreads();                       // all dsmem stores issued
        if (tid < 8) mbar_arrive_remote(mbar, tid);
        if (tid < 256 && step < 127) {         // prefetch next xg under peers' tails
            int tn = dir ? (126 - step) : (step + 1);
            xreg = xg[(((gbg << 7) + tn) << 10) + gxrow];
        }
    }
    // don't exit while peers' stores/arrives into this CTA may be in flight
    asm volatile("barrier.cluster.arrive.aligned;" ::: "memory");
    asm volatile("barrier.cluster.wait.aligned;"   ::: "memory");
}

// ---------------- o = 0.5*(h_f + h_b) ---------------------------------------
__global__ void combine_kernel() {
    int i = blockIdx.x * blockDim.x + threadIdx.x;
    float4 f = ((const float4*)g_hf)[i];
    float4 b = ((const float4*)g_hb)[i];
    float4 o;
    o.x = 0.5f*(f.x+b.x); o.y = 0.5f*(f.y+b.y);
    o.z = 0.5f*(f.z+b.z); o.w = 0.5f*(f.w+b.w);
    ((float4*)g_o)[i] = o;
}

// ---------------- CRF: emi projection + forward algorithm -------------------
__global__ __launch_bounds__(128) void crf_kernel(
    const int* __restrict__ tokens, const int* __restrict__ bio_gold,
    const float* __restrict__ emi_W, const float* __restrict__ emi_b,
    const float* __restrict__ crf_start, const float* __restrict__ crf_end,
    const float* __restrict__ crf_trans)
{
    int b = blockIdx.x;
    __shared__ float emi_s[128][3];
    __shared__ float Wsh[768];
    __shared__ float bsh[3], st[3], en[3], tr[9];
    __shared__ float msk[128];
    __shared__ int   bio_s[128];
    int tid = threadIdx.x;
    for (int e = tid; e < 768; e += 128) Wsh[e] = emi_W[e];
    if (tid < 3) { bsh[tid]=emi_b[tid]; st[tid]=crf_start[tid]; en[tid]=crf_end[tid]; }
    if (tid < 9) tr[tid] = crf_trans[tid];
    bio_s[tid] = bio_gold[b * 128 + tid];
    msk[tid]   = (tokens[b * 128 + tid] != 0) ? 1.f : 0.f;
    __syncthreads();
    {
        const float4* orow = (const float4*)(g_o + (b * 128 + tid) * 256);
        float a0=0.f, a1=0.f, a2=0.f;
#pragma unroll 4
        for (int k = 0; k < 64; ++k) {
            float4 ov = orow[k];
            const float* w0 = &Wsh[4*k];
            const float* w1 = &Wsh[256 + 4*k];
            const float* w2 = &Wsh[512 + 4*k];
            a0 += ov.x*w0[0] + ov.y*w0[1] + ov.z*w0[2] + ov.w*w0[3];
            a1 += ov.x*w1[0] + ov.y*w1[1] + ov.z*w1[2] + ov.w*w1[3];
            a2 += ov.x*w2[0] + ov.y*w2[1] + ov.z*w2[2] + ov.w*w2[3];
        }
        emi_s[tid][0] = a0 + bsh[0];
        emi_s[tid][1] = a1 + bsh[1];
        emi_s[tid][2] = a2 + bsh[2];
    }
    __syncthreads();
    if (tid < 32) {
        float score = 0.f;
        if (tid < 3) score = st[tid] + emi_s[0][tid];
        for (int t = 1; t < 128; ++t) {
            float s0 = __shfl_sync(0xffffffffu, score, 0);
            float s1 = __shfl_sync(0xffffffffu, score, 1);
            float s2 = __shfl_sync(0xffffffffu, score, 2);
            if (tid < 3) {
                float x0 = s0 + tr[tid];
                float x1 = s1 + tr[3 + tid];
                float x2 = s2 + tr[6 + tid];
                float mx = fmaxf(x0, fmaxf(x1, x2));
                float l  = mx + logf(expf(x0-mx) + expf(x1-mx) + expf(x2-mx))
                           + emi_s[t][tid];
                if (msk[t] > 0.f) score = l;
            }
        }
        float f0 = __shfl_sync(0xffffffffu, score, 0) + en[0];
        float f1 = __shfl_sync(0xffffffffu, score, 1) + en[1];
        float f2 = __shfl_sync(0xffffffffu, score, 2) + en[2];
        if (tid == 0) {
            float mx  = fmaxf(f0, fmaxf(f1, f2));
            float den = mx + logf(expf(f0-mx) + expf(f1-mx) + expf(f2-mx));
            float num = st[bio_s[0]] + emi_s[0][bio_s[0]];
            int cnt = 0;
            for (int t = 0; t < 128; ++t) if (msk[t] > 0.f) ++cnt;
            for (int t = 1; t < 128; ++t)
                num += (tr[bio_s[t-1]*3 + bio_s[t]] + emi_s[t][bio_s[t]]) * msk[t];
            int se = cnt - 1; if (se < 0) se = 0;
            num += en[bio_s[se]];
            g_crf[b] = num - den;
        }
    }
}

// ---------------- selection head: logits + masked BCE partial sums ----------
__global__ __launch_bounds__(256) void sel_kernel(
    const float* __restrict__ rel_emb, const float* __restrict__ Y,
    const int* __restrict__ tokens)
{
    __shared__ float a_s [128*33];
    __shared__ float cb_s[128*17];
    __shared__ float rel_s[128*25];
    __shared__ float mI[16], mJ[32], red[8];
    int b  = blockIdx.y;
    int i0 = (blockIdx.x >> 2) * 16, j0 = (blockIdx.x & 3) * 32;
    int tid = threadIdx.x;
    for (int e = tid; e < 32*128; e += 256) {
        int j = e >> 7, h = e & 127;
        a_s[h*33 + j] = g_a[(b*128 + j0 + j)*128 + h];
    }
    for (int e = tid; e < 16*128; e += 256) {
        int i = e >> 7, h = e & 127;
        cb_s[h*17 + i] = g_cb[(b*128 + i0 + i)*128 + h];
    }
    for (int e = tid; e < 25*128; e += 256) {
        int r = e >> 7, h = e & 127;
        rel_s[h*25 + r] = rel_emb[r*128 + h];
    }
    if (tid < 32) mJ[tid] = (tokens[b*128 + j0 + tid] != 0) ? 1.f : 0.f;
    if (tid < 16) mI[tid] = (tokens[b*128 + i0 + tid] != 0) ? 1.f : 0.f;
    __syncthreads();

    int j = tid & 31, ia = tid >> 5, ib = ia + 8;
    float acc0[25], acc1[25];
#pragma unroll
    for (int r = 0; r < 25; ++r) { acc0[r] = 0.f; acc1[r] = 0.f; }
    for (int h = 0; h < 128; ++h) {
        float av = a_s[h*33 + j];
        float u0 = fmaxf(av + cb_s[h*17 + ia], 0.f);
        float u1 = fmaxf(av + cb_s[h*17 + ib], 0.f);
        const float* rp = &rel_s[h*25];
#pragma unroll
        for (int r = 0; r < 25; ++r) {
            float rv = rp[r];
            acc0[r] = fmaf(u0, rv, acc0[r]);
            acc1[r] = fmaf(u1, rv, acc1[r]);
        }
    }
    float mj = mJ[j];
    float m0 = mI[ia]*mj, m1 = mI[ib]*mj;
    int gi0 = b*128 + i0 + ia, gi1 = b*128 + i0 + ib;
    float tsum = 0.f;
#pragma unroll
    for (int r = 0; r < 25; ++r) {
        float l = acc0[r];
        float y = Y[(gi0*25 + r)*128 + j0 + j];
        tsum += m0 * (fmaxf(l,0.f) - l*y + log1pf(expf(-fabsf(l))));
        l = acc1[r];
        y = Y[(gi1*25 + r)*128 + j0 + j];
        tsum += m1 * (fmaxf(l,0.f) - l*y + log1pf(expf(-fabsf(l))));
    }
    for (int off = 16; off; off >>= 1)
        tsum += __shfl_down_sync(0xffffffffu, tsum, off);
    if ((tid & 31) == 0) red[tid >> 5] = tsum;
    __syncthreads();
    if (tid < 8) {
        float v2 = red[tid];
        for (int off = 4; off; off >>= 1)
            v2 += __shfl_down_sync(0xffu, v2, off);
        if (tid == 0) g_selpart[blockIdx.y*32 + blockIdx.x] = v2;
    }
}

// ---------------- final deterministic reduction ------------------------------
__global__ __launch_bounds__(512) void final_kernel(const int* __restrict__ tokens,
                                                    float* __restrict__ out)
{
    __shared__ float sh[512];
    __shared__ int csh[512];
    int tid = threadIdx.x;
    int cnt = 0;
    for (int e = tid; e < 2048; e += 512) cnt += (tokens[e] != 0);
    sh[tid] = g_selpart[tid];
    csh[tid] = cnt;
    __syncthreads();
    for (int off = 256; off; off >>= 1) {
        if (tid < off) { sh[tid] += sh[tid+off]; csh[tid] += csh[tid+off]; }
        __syncthreads();
    }
    if (tid == 0) {
        float crf = 0.f;
        for (int b = 0; b < 16; ++b) crf += g_crf[b];
        out[0] = -(crf / 16.f) + sh[0] / (float)csh[0];
    }
}

// ---------------- launch -----------------------------------------------------
extern "C" void kernel_launch(void* const* d_in, const int* in_sizes, int n_in,
                              void* d_out, int out_size)
{
    const int*   tokens    = (const int*)  d_in[0];
    const int*   bio_gold  = (const int*)  d_in[1];
    const float* sel_gold  = (const float*)d_in[2];
    const float* word_emb  = (const float*)d_in[3];
    const float* W_ih_f    = (const float*)d_in[4];
    const float* W_hh_f    = (const float*)d_in[5];
    const float* b_f       = (const float*)d_in[6];
    const float* W_ih_b    = (const float*)d_in[7];
    const float* W_hh_b    = (const float*)d_in[8];
    const float* b_b       = (const float*)d_in[9];
    const float* emi_W     = (const float*)d_in[10];
    const float* emi_b     = (const float*)d_in[11];
    const float* bio_emb   = (const float*)d_in[12];
    const float* sel_u_W   = (const float*)d_in[13];
    const float* sel_u_b   = (const float*)d_in[14];
    const float* sel_v_W   = (const float*)d_in[15];
    const float* sel_v_b   = (const float*)d_in[16];
    const float* sel_uv_W  = (const float*)d_in[17];
    const float* sel_uv_b  = (const float*)d_in[18];
    const float* rel_emb   = (const float*)d_in[19];
    const float* crf_start = (const float*)d_in[20];
    const float* crf_end   = (const float*)d_in[21];
    const float* crf_trans = (const float*)d_in[22];
    float* out = (float*)d_out;

    float *p_xg_f, *p_xg_b, *p_u, *p_v, *p_a, *p_cb;
    cudaGetSymbolAddress((void**)&p_xg_f, g_xg_f);
    cudaGetSymbolAddress((void**)&p_xg_b, g_xg_b);
    cudaGetSymbolAddress((void**)&p_u,  g_u);
    cudaGetSymbolAddress((void**)&p_v,  g_v);
    cudaGetSymbolAddress((void**)&p_a,  g_a);
    cudaGetSymbolAddress((void**)&p_cb, g_cb);

    const int LSTM_SMEM = (4 + 32768 + 1024 + 2560) * 4;   // 145424 B
    cudaFuncSetAttribute(lstm_cluster_kernel,
                         cudaFuncAttributeMaxDynamicSharedMemorySize, LSTM_SMEM);

    // 0. prep weight slices (k-major, per dir/slice)
    prep_kernel<<<dim3(32, 8, 2), 256>>>(W_hh_f, W_hh_b);

    // 1. input-gate GEMMs (both directions in one z-paired launch)
    gemm_kernel<<<dim3(16,32,2), 256>>>(256, 1,
        nullptr, nullptr, 0, tokens, word_emb, nullptr, nullptr,
        W_ih_f, W_ih_b, 256, b_f, b_b, 0, p_xg_f, p_xg_b, 1024);

    // 2. BiLSTM recurrence (mbarrier-synced cluster)
    lstm_cluster_kernel<<<128, 512, LSTM_SMEM>>>();

    // 3. o = 0.5*(hf + hb)
    combine_kernel<<<512, 256>>>();

    // 4. CRF loss (per-batch partials)
    crf_kernel<<<16, 128>>>(tokens, bio_gold, emi_W, emi_b,
                            crf_start, crf_end, crf_trans);

    // 5. u/v = relu(oc @ W^T + b) (paired)
    gemm_kernel<<<dim3(2,32,2), 256>>>(320, 2,
        nullptr, nullptr, 0, nullptr, nullptr, bio_gold, bio_emb,
        sel_u_W, sel_v_W, 320, sel_u_b, sel_v_b, 1, p_u, p_v, 128);

    // 6. a = u @ W1^T ; cb = v @ W2^T + sel_uv_b (paired)
    gemm_kernel<<<dim3(2,32,2), 256>>>(128, 0,
        p_u, p_v, 128, nullptr, nullptr, nullptr, nullptr,
        sel_uv_W, sel_uv_W + 128, 256, nullptr, sel_uv_b, 0, p_a, p_cb, 128);

    // 7. selection BCE partial sums
    sel_kernel<<<dim3(32,16), 256>>>(rel_emb, sel_gold, tokens);

    // 8. final reduction -> scalar loss
    final_kernel<<<1, 512>>>(tokens, out);
}

// round 15
// speedup vs baseline: 1.0862x; 1.0862x over previous
#include <cuda_runtime.h>
#include <math.h>

// ---------------- scratch (static device globals) ---------------------------
__device__ float g_xg_f[16*128*1024];
__device__ float g_xg_b[16*128*1024];
__device__ float g_Wsl[2*8*256*128];   // per (dir,slice): k-major [256][128]
__device__ float g_hf [16*128*256];
__device__ float g_hb [16*128*256];
__device__ float g_o  [16*128*256];
__device__ float g_u  [2048*128];
__device__ float g_v  [2048*128];
__device__ float g_a  [2048*128];
__device__ float g_cb [2048*128];
__device__ float g_crf[16];
__device__ float g_selpart[512];

// ---------------- generic 64x64 SGEMM: C = op(A) @ W^T (+bias)(relu) --------
// amode: 0 = A[row*lda+k]; 1 = word_emb[tokens[row]*256+k];
//        2 = k<256 ? g_o[row*256+k] : bio_emb[bio_gold[row]*64+(k-256)]
__global__ __launch_bounds__(256) void gemm_kernel(
    int K, int amode,
    const float* __restrict__ A, int lda,
    const int*   __restrict__ tokens,
    const float* __restrict__ word_emb,
    const int*   __restrict__ bio_gold,
    const float* __restrict__ bio_emb,
    const float* __restrict__ W, int ldw,
    const float* __restrict__ bias, int do_relu,
    float* __restrict__ C, int ldc)
{
    __shared__ __align__(16) float As[16][68];
    __shared__ __align__(16) float Bs[16][68];
    int tid = threadIdx.x;
    int tx = tid & 15, ty = tid >> 4;
    int row0 = blockIdx.y * 64, col0 = blockIdx.x * 64;
    float acc[4][4];
#pragma unroll
    for (int i = 0; i < 4; ++i)
#pragma unroll
        for (int j = 0; j < 4; ++j) acc[i][j] = 0.f;

    for (int k0 = 0; k0 < K; k0 += 16) {
#pragma unroll
        for (int l = 0; l < 4; ++l) {
            int e = tid + l * 256;
            int m = e >> 4, kk = e & 15;
            int row = row0 + m, k = k0 + kk;
            float v;
            if (amode == 0)      v = A[row * lda + k];
            else if (amode == 1) v = word_emb[tokens[row] * 256 + k];
            else                 v = (k < 256) ? g_o[row * 256 + k]
                                               : bio_emb[bio_gold[row] * 64 + (k - 256)];
            As[kk][m] = v;
            Bs[kk][m] = W[(col0 + m) * ldw + k];
        }
        __syncthreads();
#pragma unroll
        for (int kk = 0; kk < 16; ++kk) {
            float4 a4 = *(const float4*)&As[kk][ty << 2];
            float4 b4 = *(const float4*)&Bs[kk][tx << 2];
            acc[0][0]=fmaf(a4.x,b4.x,acc[0][0]); acc[0][1]=fmaf(a4.x,b4.y,acc[0][1]);
            acc[0][2]=fmaf(a4.x,b4.z,acc[0][2]); acc[0][3]=fmaf(a4.x,b4.w,acc[0][3]);
            acc[1][0]=fmaf(a4.y,b4.x,acc[1][0]); acc[1][1]=fmaf(a4.y,b4.y,acc[1][1]);
            acc[1][2]=fmaf(a4.y,b4.z,acc[1][2]); acc[1][3]=fmaf(a4.y,b4.w,acc[1][3]);
            acc[2][0]=fmaf(a4.z,b4.x,acc[2][0]); acc[2][1]=fmaf(a4.z,b4.y,acc[2][1]);
            acc[2][2]=fmaf(a4.z,b4.z,acc[2][2]); acc[2][3]=fmaf(a4.z,b4.w,acc[2][3]);
            acc[3][0]=fmaf(a4.w,b4.x,acc[3][0]); acc[3][1]=fmaf(a4.w,b4.y,acc[3][1]);
            acc[3][2]=fmaf(a4.w,b4.z,acc[3][2]); acc[3][3]=fmaf(a4.w,b4.w,acc[3][3]);
        }
        __syncthreads();
    }
#pragma unroll
    for (int i = 0; i < 4; ++i) {
        int row = row0 + (ty << 2) + i;
#pragma unroll
        for (int j = 0; j < 4; ++j) {
            int col = col0 + (tx << 2) + j;
            float v = acc[i][j];
            if (bias) v += bias[col];
            if (do_relu) v = fmaxf(v, 0.f);
            C[row * ldc + col] = v;
        }
    }
}

// ---------------- prep: W_hh -> per-(dir,slice) k-major slices --------------
// g_Wsl[(dir*8+s)*32768 + k*128 + (g*32+u)] = W[(g*256 + s*32 + u)*256 + k]
__global__ __launch_bounds__(256) void prep_kernel(
    const float* __restrict__ Wf, const float* __restrict__ Wb)
{
    __shared__ float tile[32][33];
    int dir = blockIdx.z;
    const float* W = dir ? Wb : Wf;
    int R0 = blockIdx.x * 32;
    int k0 = blockIdx.y * 32;
    int g = R0 >> 8;
    int s = (R0 >> 5) & 7;
    int tx = threadIdx.x & 31, ty = threadIdx.x >> 5;
#pragma unroll
    for (int l = 0; l < 4; ++l)
        tile[ty + 8*l][tx] = W[(R0 + ty + 8*l) * 256 + k0 + tx];
    __syncthreads();
    float* dst = g_Wsl + ((dir*8 + s) << 15);
#pragma unroll
    for (int l = 0; l < 4; ++l)
        dst[(k0 + ty + 8*l) * 128 + g*32 + tx] = tile[tx][ty + 8*l];
}

// ---------------- DSMEM helpers ---------------------------------------------
__device__ __forceinline__ unsigned smem_u32(const void* p) {
    unsigned a;
    asm("{ .reg .u64 t; cvta.to.shared.u64 t, %1; cvt.u32.u64 %0, t; }"
        : "=r"(a) : "l"(p));
    return a;
}
__device__ __forceinline__ unsigned cta_rank() {
    unsigned r; asm("mov.u32 %0, %%cluster_ctarank;" : "=r"(r)); return r;
}
__device__ __forceinline__ void dsmem_st(unsigned laddr, int rank, float v) {
    unsigned raddr;
    asm volatile("mapa.shared::cluster.u32 %0, %1, %2;"
                 : "=r"(raddr) : "r"(laddr), "r"(rank));
    asm volatile("st.shared::cluster.f32 [%0], %1;"
                 :: "r"(raddr), "f"(v) : "memory");
}

// ---------------- BiLSTM: register-resident weights, DSMEM h exchange -------
// 16 clusters x 8 CTAs; CTA (rank=slice) owns 32 units (128 gate rows) for
// 2 batches. 512 threads: 64 rowpairs x 8 k-octants. Each thread holds its
// 64 step-invariant weights in registers; k-loop = 16 broadcast LDS + 128 FMA.
__global__ void __cluster_dims__(8,1,1) __launch_bounds__(512) lstm_cluster_kernel()
{
    int slice = cta_rank();
    int cl  = blockIdx.x >> 3;       // 0..15
    int dir = cl >> 3, pair = cl & 7;
    const float* xg = dir ? g_xg_b : g_xg_f;
    float* hout     = dir ? g_hb : g_hf;
    __shared__ __align__(16) float h_s[1024];   // [2 phase][2 batch][256]
    __shared__ float part[2048];                 // [8 q][2 b][128]
    int tid = threadIdx.x;
    int rp = tid & 63, kq = tid >> 6;
    int r0 = rp << 1, kbase = kq << 5;
    int cu = tid & 31, cbb = (tid >> 5) & 1;     // tail roles (tid<64)
    unsigned hx_addr = 0;
    if (tid < 64)
        hx_addr = smem_u32(&h_s[(cbb << 8) + (slice << 5) + cu]);

    // hoist step-invariant weights into registers (coalesced float2 LDG)
    const float* gw = g_Wsl + ((dir*8 + slice) << 15);
    float2 wreg[32];
#pragma unroll
    for (int kl = 0; kl < 32; ++kl)
        wreg[kl] = *(const float2*)&gw[((kbase + kl) << 7) + r0];

    float cst = 0.f;
    h_s[tid] = 0.f;                  // zero phase-0 buffer
    __syncthreads();

    for (int step = 0; step < 128; ++step) {
        int t = dir ? (127 - step) : step;
        int phase = step & 1;
        const float* hp = h_s + (phase << 9);
        float xgv0 = 0.f, xgv1 = 0.f, xgv2 = 0.f, xgv3 = 0.f;
        if (tid < 64) {   // xg values for this unit (4 gates)
            int bg = (pair << 1) + cbb;
            const float* xrow = xg + (((bg << 7) + t) << 10) + (slice << 5) + cu;
            xgv0 = xrow[0]; xgv1 = xrow[256]; xgv2 = xrow[512]; xgv3 = xrow[768];
        }

        float a00 = 0.f, a10 = 0.f, a01 = 0.f, a11 = 0.f;
#pragma unroll
        for (int kl = 0; kl < 32; kl += 4) {
            int k = kbase + kl;
            float4 ha4 = *(const float4*)&hp[k];
            float4 hb4 = *(const float4*)&hp[256 + k];
            float2 w0 = wreg[kl], w1 = wreg[kl+1], w2 = wreg[kl+2], w3 = wreg[kl+3];
            a00 = fmaf(w0.x, ha4.x, a00); a10 = fmaf(w0.y, ha4.x, a10);
            a01 = fmaf(w0.x, hb4.x, a01); a11 = fmaf(w0.y, hb4.x, a11);
            a00 = fmaf(w1.x, ha4.y, a00); a10 = fmaf(w1.y, ha4.y, a10);
            a01 = fmaf(w1.x, hb4.y, a01); a11 = fmaf(w1.y, hb4.y, a11);
            a00 = fmaf(w2.x, ha4.z, a00); a10 = fmaf(w2.y, ha4.z, a10);
            a01 = fmaf(w2.x, hb4.z, a01); a11 = fmaf(w2.y, hb4.z, a11);
            a00 = fmaf(w3.x, ha4.w, a00); a10 = fmaf(w3.y, ha4.w, a10);
            a01 = fmaf(w3.x, hb4.w, a01); a11 = fmaf(w3.y, hb4.w, a11);
        }
        part[(kq << 8) + r0]           = a00;
        part[(kq << 8) + r0 + 1]       = a10;
        part[(kq << 8) + 128 + r0]     = a01;
        part[(kq << 8) + 128 + r0 + 1] = a11;
        __syncthreads();
        if (tid < 64) {
            float gi = xgv0, gf = xgv1, gg = xgv2, go = xgv3;
#pragma unroll
            for (int q = 0; q < 8; ++q) {
                const float* pb = part + (q << 8) + (cbb << 7);
                gi += pb[cu]; gf += pb[32 + cu]; gg += pb[64 + cu]; go += pb[96 + cu];
            }
            float si = 1.f / (1.f + expf(-gi));
            float sf = 1.f / (1.f + expf(-gf));
            float so = 1.f / (1.f + expf(-go));
            cst = sf * cst + si * tanhf(gg);
            float h = so * tanhf(cst);
            int bg = (pair << 1) + cbb;
            hout[(((bg << 7) + t) << 8) + (slice << 5) + cu] = h;
            unsigned dsta = hx_addr + ((phase ^ 1) << 11);   // other phase buffer
#pragma unroll
            for (int rk = 0; rk < 8; ++rk) dsmem_st(dsta, rk, h);
        }
        asm volatile("barrier.cluster.arrive.aligned;" ::: "memory");
        asm volatile("barrier.cluster.wait.aligned;"   ::: "memory");
    }
}

// ---------------- o = 0.5*(h_f + h_b) ---------------------------------------
__global__ void combine_kernel() {
    int i = blockIdx.x * blockDim.x + threadIdx.x;
    float4 f = ((const float4*)g_hf)[i];
    float4 b = ((const float4*)g_hb)[i];
    float4 o;
    o.x = 0.5f*(f.x+b.x); o.y = 0.5f*(f.y+b.y);
    o.z = 0.5f*(f.z+b.z); o.w = 0.5f*(f.w+b.w);
    ((float4*)g_o)[i] = o;
}

// ---------------- CRF: emi projection + forward algorithm -------------------
__global__ __launch_bounds__(128) void crf_kernel(
    const int* __restrict__ tokens, const int* __restrict__ bio_gold,
    const float* __restrict__ emi_W, const float* __restrict__ emi_b,
    const float* __restrict__ crf_start, const float* __restrict__ crf_end,
    const float* __restrict__ crf_trans)
{
    int b = blockIdx.x;
    __shared__ float emi_s[128][3];
    __shared__ float Wsh[768];
    __shared__ float bsh[3], st[3], en[3], tr[9];
    __shared__ float msk[128];
    __shared__ int   bio_s[128];
    int tid = threadIdx.x;
    for (int e = tid; e < 768; e += 128) Wsh[e] = emi_W[e];
    if (tid < 3) { bsh[tid]=emi_b[tid]; st[tid]=crf_start[tid]; en[tid]=crf_end[tid]; }
    if (tid < 9) tr[tid] = crf_trans[tid];
    bio_s[tid] = bio_gold[b * 128 + tid];
    msk[tid]   = (tokens[b * 128 + tid] != 0) ? 1.f : 0.f;
    __syncthreads();
    {
        const float4* orow = (const float4*)(g_o + (b * 128 + tid) * 256);
        float a0=0.f, a1=0.f, a2=0.f;
#pragma unroll 4
        for (int k = 0; k < 64; ++k) {
            float4 ov = orow[k];
            const float* w0 = &Wsh[4*k];
            const float* w1 = &Wsh[256 + 4*k];
            const float* w2 = &Wsh[512 + 4*k];
            a0 += ov.x*w0[0] + ov.y*w0[1] + ov.z*w0[2] + ov.w*w0[3];
            a1 += ov.x*w1[0] + ov.y*w1[1] + ov.z*w1[2] + ov.w*w1[3];
            a2 += ov.x*w2[0] + ov.y*w2[1] + ov.z*w2[2] + ov.w*w2[3];
        }
        emi_s[tid][0] = a0 + bsh[0];
        emi_s[tid][1] = a1 + bsh[1];
        emi_s[tid][2] = a2 + bsh[2];
    }
    __syncthreads();
    if (tid < 32) {
        float score = 0.f;
        if (tid < 3) score = st[tid] + emi_s[0][tid];
        for (int t = 1; t < 128; ++t) {
            float s0 = __shfl_sync(0xffffffffu, score, 0);
            float s1 = __shfl_sync(0xffffffffu, score, 1);
            float s2 = __shfl_sync(0xffffffffu, score, 2);
            if (tid < 3) {
                float x0 = s0 + tr[tid];
                float x1 = s1 + tr[3 + tid];
                float x2 = s2 + tr[6 + tid];
                float mx = fmaxf(x0, fmaxf(x1, x2));
                float l  = mx + logf(expf(x0-mx) + expf(x1-mx) + expf(x2-mx))
                           + emi_s[t][tid];
                if (msk[t] > 0.f) score = l;
            }
        }
        float f0 = __shfl_sync(0xffffffffu, score, 0) + en[0];
        float f1 = __shfl_sync(0xffffffffu, score, 1) + en[1];
        float f2 = __shfl_sync(0xffffffffu, score, 2) + en[2];
        if (tid == 0) {
            float mx  = fmaxf(f0, fmaxf(f1, f2));
            float den = mx + logf(expf(f0-mx) + expf(f1-mx) + expf(f2-mx));
            float num = st[bio_s[0]] + emi_s[0][bio_s[0]];
            int cnt = 0;
            for (int t = 0; t < 128; ++t) if (msk[t] > 0.f) ++cnt;
            for (int t = 1; t < 128; ++t)
                num += (tr[bio_s[t-1]*3 + bio_s[t]] + emi_s[t][bio_s[t]]) * msk[t];
            int se = cnt - 1; if (se < 0) se = 0;
            num += en[bio_s[se]];
            g_crf[b] = num - den;
        }
    }
}

// ---------------- selection head: logits + masked BCE partial sums ----------
__global__ __launch_bounds__(256) void sel_kernel(
    const float* __restrict__ rel_emb, const float* __restrict__ Y,
    const int* __restrict__ tokens)
{
    __shared__ float a_s [128*33];
    __shared__ float cb_s[128*17];
    __shared__ float rel_s[128*25];
    __shared__ float mI[16], mJ[32], red[8];
    int b  = blockIdx.y;
    int i0 = (blockIdx.x >> 2) * 16, j0 = (blockIdx.x & 3) * 32;
    int tid = threadIdx.x;
    for (int e = tid; e < 32*128; e += 256) {
        int j = e >> 7, h = e & 127;
        a_s[h*33 + j] = g_a[(b*128 + j0 + j)*128 + h];
    }
    for (int e = tid; e < 16*128; e += 256) {
        int i = e >> 7, h = e & 127;
        cb_s[h*17 + i] = g_cb[(b*128 + i0 + i)*128 + h];
    }
    for (int e = tid; e < 25*128; e += 256) {
        int r = e >> 7, h = e & 127;
        rel_s[h*25 + r] = rel_emb[r*128 + h];
    }
    if (tid < 32) mJ[tid] = (tokens[b*128 + j0 + tid] != 0) ? 1.f : 0.f;
    if (tid < 16) mI[tid] = (tokens[b*128 + i0 + tid] != 0) ? 1.f : 0.f;
    __syncthreads();

    int j = tid & 31, ia = tid >> 5, ib = ia + 8;
    float acc0[25], acc1[25];
#pragma unroll
    for (int r = 0; r < 25; ++r) { acc0[r] = 0.f; acc1[r] = 0.f; }
    for (int h = 0; h < 128; ++h) {
        float av = a_s[h*33 + j];
        float u0 = fmaxf(av + cb_s[h*17 + ia], 0.f);
        float u1 = fmaxf(av + cb_s[h*17 + ib], 0.f);
        const float* rp = &rel_s[h*25];
#pragma unroll
        for (int r = 0; r < 25; ++r) {
            float rv = rp[r];
            acc0[r] = fmaf(u0, rv, acc0[r]);
            acc1[r] = fmaf(u1, rv, acc1[r]);
        }
    }
    float mj = mJ[j];
    float m0 = mI[ia]*mj, m1 = mI[ib]*mj;
    int gi0 = b*128 + i0 + ia, gi1 = b*128 + i0 + ib;
    float tsum = 0.f;
#pragma unroll
    for (int r = 0; r < 25; ++r) {
        float l = acc0[r];
        float y = Y[(gi0*25 + r)*128 + j0 + j];
        tsum += m0 * (fmaxf(l,0.f) - l*y + log1pf(expf(-fabsf(l))));
        l = acc1[r];
        y = Y[(gi1*25 + r)*128 + j0 + j];
        tsum += m1 * (fmaxf(l,0.f) - l*y + log1pf(expf(-fabsf(l))));
    }
    for (int off = 16; off; off >>= 1)
        tsum += __shfl_down_sync(0xffffffffu, tsum, off);
    if ((tid & 31) == 0) red[tid >> 5] = tsum;
    __syncthreads();
    if (tid < 8) {
        float v2 = red[tid];
        for (int off = 4; off; off >>= 1)
            v2 += __shfl_down_sync(0xffu, v2, off);
        if (tid == 0) g_selpart[blockIdx.y*32 + blockIdx.x] = v2;
    }
}

// ---------------- final deterministic reduction ------------------------------
__global__ __launch_bounds__(512) void final_kernel(const int* __restrict__ tokens,
                                                    float* __restrict__ out)
{
    __shared__ float sh[512];
    __shared__ int csh[512];
    int tid = threadIdx.x;
    int cnt = 0;
    for (int e = tid; e < 2048; e += 512) cnt += (tokens[e] != 0);
    sh[tid] = g_selpart[tid];
    csh[tid] = cnt;
    __syncthreads();
    for (int off = 256; off; off >>= 1) {
        if (tid < off) { sh[tid] += sh[tid+off]; csh[tid] += csh[tid+off]; }
        __syncthreads();
    }
    if (tid == 0) {
        float crf = 0.f;
        for (int b = 0; b < 16; ++b) crf += g_crf[b];
        out[0] = -(crf / 16.f) + sh[0] / (float)csh[0];
    }
}

// ---------------- launch -----------------------------------------------------
extern "C" void kernel_launch(void* const* d_in, const int* in_sizes, int n_in,
                              void* d_out, int out_size)
{
    const int*   tokens    = (const int*)  d_in[0];
    const int*   bio_gold  = (const int*)  d_in[1];
    const float* sel_gold  = (const float*)d_in[2];
    const float* word_emb  = (const float*)d_in[3];
    const float* W_ih_f    = (const float*)d_in[4];
    const float* W_hh_f    = (const float*)d_in[5];
    const float* b_f       = (const float*)d_in[6];
    const float* W_ih_b    = (const float*)d_in[7];
    const float* W_hh_b    = (const float*)d_in[8];
    const float* b_b       = (const float*)d_in[9];
    const float* emi_W     = (const float*)d_in[10];
    const float* emi_b     = (const float*)d_in[11];
    const float* bio_emb   = (const float*)d_in[12];
    const float* sel_u_W   = (const float*)d_in[13];
    const float* sel_u_b   = (const float*)d_in[14];
    const float* sel_v_W   = (const float*)d_in[15];
    const float* sel_v_b   = (const float*)d_in[16];
    const float* sel_uv_W  = (const float*)d_in[17];
    const float* sel_uv_b  = (const float*)d_in[18];
    const float* rel_emb   = (const float*)d_in[19];
    const float* crf_start = (const float*)d_in[20];
    const float* crf_end   = (const float*)d_in[21];
    const float* crf_trans = (const float*)d_in[22];
    float* out = (float*)d_out;

    float *p_xg_f, *p_xg_b, *p_u, *p_v, *p_a, *p_cb;
    cudaGetSymbolAddress((void**)&p_xg_f, g_xg_f);
    cudaGetSymbolAddress((void**)&p_xg_b, g_xg_b);
    cudaGetSymbolAddress((void**)&p_u,  g_u);
    cudaGetSymbolAddress((void**)&p_v,  g_v);
    cudaGetSymbolAddress((void**)&p_a,  g_a);
    cudaGetSymbolAddress((void**)&p_cb, g_cb);

    // 0. prep weight slices (k-major, per dir/slice)
    prep_kernel<<<dim3(32, 8, 2), 256>>>(W_hh_f, W_hh_b);

    // 1. input-gate GEMMs: xg = emb @ W_ih^T + b   (M=2048, N=1024, K=256)
    gemm_kernel<<<dim3(16,32), 256>>>(256, 1, nullptr, 0, tokens, word_emb,
        nullptr, nullptr, W_ih_f, 256, b_f, 0, p_xg_f, 1024);
    gemm_kernel<<<dim3(16,32), 256>>>(256, 1, nullptr, 0, tokens, word_emb,
        nullptr, nullptr, W_ih_b, 256, b_b, 0, p_xg_b, 1024);

    // 2. BiLSTM recurrence: register-resident weights, DSMEM h exchange
    lstm_cluster_kernel<<<128, 512>>>();

    // 3. o = 0.5*(hf + hb)
    combine_kernel<<<512, 256>>>();

    // 4. CRF loss (per-batch partials)
    crf_kernel<<<16, 128>>>(tokens, bio_gold, emi_W, emi_b,
                            crf_start, crf_end, crf_trans);

    // 5. u/v = relu(oc @ W^T + b)  (M=2048, N=128, K=320)
    gemm_kernel<<<dim3(2,32), 256>>>(320, 2, nullptr, 0, nullptr, nullptr,
        bio_gold, bio_emb, sel_u_W, 320, sel_u_b, 1, p_u, 128);
    gemm_kernel<<<dim3(2,32), 256>>>(320, 2, nullptr, 0, nullptr, nullptr,
        bio_gold, bio_emb, sel_v_W, 320, sel_v_b, 1, p_v, 128);

    // 6. a = u @ W1^T ; cb = v @ W2^T + sel_uv_b  (M=2048, N=128, K=128)
    gemm_kernel<<<dim3(2,32), 256>>>(128, 0, p_u, 128, nullptr, nullptr,
        nullptr, nullptr, sel_uv_W, 256, nullptr, 0, p_a, 128);
    gemm_kernel<<<dim3(2,32), 256>>>(128, 0, p_v, 128, nullptr, nullptr,
        nullptr, nullptr, sel_uv_W + 128, 256, sel_uv_b, 0, p_cb, 128);

    // 7. selection BCE partial sums
    sel_kernel<<<dim3(32,16), 256>>>(rel_emb, sel_gold, tokens);

    // 8. final reduction -> scalar loss
    final_kernel<<<1, 512>>>(tokens, out);
}